// round 8
// baseline (speedup 1.0000x reference)
#include <cuda_runtime.h>
#include <cuda_bf16.h>
#include <cuda_fp16.h>
#include <cstdint>

#define THREADS 256
#define HID 100
#define NC 30
#define SD 10
#define BETA_F 3.0f
#define MAXA_F 5.0f

typedef unsigned long long ull;

// ---- constant bank (layer-1 weights, K-pair packed) ----
#define CW1T 0       // [100][5] (W1[2p][j], W1[2p+1][j])
#define CL1T 500
#define CB1  1000    // (b1[j], 0)
#define CBL1 1100
#define CONST_ULL 1200
__constant__ ull cb[CONST_ULL];
__device__ ull d_scratch[CONST_ULL];

// ---- B fragments (precomputed in mma fragment-lane order) ----
#define NFRAG_LOC (7 * 8 * 32)   // 7 k-chunks x 8 n-tiles x 32 lanes
#define NFRAG_VAL (7 * 4 * 32)
__device__ uint4 d_bfrag[NFRAG_LOC + NFRAG_VAL];

// ---- SMEM byte layout ----
#define SM_BF   0                         // 2688 * 16 = 43008
#define SM_HT   43008                     // per warp 2 bufs x (hi 1536 + lo 1536) = 6144; 8 warps = 49152
#define SM_EW   92160                     // per warp 32 rows * 40 halves * 2B = 2560; 8 warps = 20480
#define SMEM_BYTES 112640

__device__ __forceinline__ ull pk2(float x, float y) {
    ull r; asm("mov.b64 %0, {%1, %2};" : "=l"(r) : "f"(x), "f"(y)); return r;
}
__device__ __forceinline__ float2 unpk(ull v) {
    float2 r; asm("mov.b64 {%0, %1}, %2;" : "=f"(r.x), "=f"(r.y) : "l"(v)); return r;
}
__device__ __forceinline__ ull ffma2(ull a, ull b, ull c) {
    ull d; asm("fma.rn.f32x2 %0, %1, %2, %3;" : "=l"(d) : "l"(a), "l"(b), "l"(c)); return d;
}
__device__ __forceinline__ float tanh_fast(float x) {
    float e = __expf(2.0f * x);
    return 1.0f - __fdividef(2.0f, e + 1.0f);
}
__device__ __forceinline__ uint32_t smem_u32(const void* p) {
    uint32_t a;
    asm("{ .reg .u64 t; cvta.to.shared.u64 t, %1; cvt.u32.u64 %0, t; }" : "=r"(a) : "l"(p));
    return a;
}
__device__ __forceinline__ void mma_bf16(float* c, const uint32_t* A,
                                         uint32_t b0, uint32_t b1) {
    asm volatile(
        "mma.sync.aligned.m16n8k16.row.col.f32.bf16.bf16.f32 "
        "{%0,%1,%2,%3}, {%4,%5,%6,%7}, {%8,%9}, {%0,%1,%2,%3};"
        : "+f"(c[0]), "+f"(c[1]), "+f"(c[2]), "+f"(c[3])
        : "r"(A[0]), "r"(A[1]), "r"(A[2]), "r"(A[3]), "r"(b0), "r"(b1));
}
__device__ __forceinline__ void ldmA(uint32_t* A, uint32_t addr) {
    asm volatile("ldmatrix.sync.aligned.m8n8.x4.shared.b16 {%0,%1,%2,%3}, [%4];"
                 : "=r"(A[0]), "=r"(A[1]), "=r"(A[2]), "=r"(A[3]) : "r"(addr));
}

// ---- prep: layer1 weights -> scratch (for constant); layer2 -> B fragments ----
extern "C" __global__ void prep_kernel(const float* __restrict__ W1,
                                       const float* __restrict__ b1,
                                       const float* __restrict__ W2,
                                       const float* __restrict__ b2,
                                       const float* __restrict__ L1,
                                       const float* __restrict__ bl1,
                                       const float* __restrict__ WL2,
                                       const float* __restrict__ bL2) {
    int t = blockIdx.x * blockDim.x + threadIdx.x;
    int stride = gridDim.x * blockDim.x;
    for (int idx = t; idx < 500; idx += stride) {
        int j = idx / 5, p = idx % 5;
        d_scratch[CW1T + idx] = pk2(W1[(2 * p) * HID + j], W1[(2 * p + 1) * HID + j]);
        d_scratch[CL1T + idx] = pk2(L1[(2 * p) * HID + j], L1[(2 * p + 1) * HID + j]);
    }
    for (int idx = t; idx < HID; idx += stride) {
        d_scratch[CB1  + idx] = pk2(b1[idx], 0.0f);
        d_scratch[CBL1 + idx] = pk2(bl1[idx], 0.0f);
    }
    for (int idx = t; idx < NFRAG_LOC + NFRAG_VAL; idx += stride) {
        bool isloc = idx < NFRAG_LOC;
        int rel = isloc ? idx : idx - NFRAG_LOC;
        int lane = rel & 31;
        int f = rel >> 5;
        int nt = isloc ? 8 : 4;
        int q = f / nt, tn = f % nt;
        int k0 = q * 16 + 2 * (lane & 3);
        int n  = tn * 8 + (lane >> 2);
        float v[4];
        #pragma unroll
        for (int e = 0; e < 4; e++) {
            int k = k0 + (e >> 1) * 8 + (e & 1);
            float x = 0.0f;
            if (isloc) {
                if (n < 60) {
                    if (k < HID)       x = WL2[(n >> 1) * 200 + k * 2 + (n & 1)];
                    else if (k == HID) x = bL2[n];
                }
            } else {
                if (n < NC) {
                    if (k < HID)       x = W2[k * NC + n];
                    else if (k == HID) x = b2[n];
                }
            }
            v[e] = x;
        }
        unsigned short hb[4], lb[4];
        #pragma unroll
        for (int e = 0; e < 4; e++) {
            __nv_bfloat16 h = __float2bfloat16(v[e]);
            hb[e] = __bfloat16_as_ushort(h);
            lb[e] = __bfloat16_as_ushort(__float2bfloat16(v[e] - __bfloat162float(h)));
        }
        uint4 o;
        o.x = (uint32_t)hb[0] | ((uint32_t)hb[1] << 16);
        o.y = (uint32_t)hb[2] | ((uint32_t)hb[3] << 16);
        o.z = (uint32_t)lb[0] | ((uint32_t)lb[1] << 16);
        o.w = (uint32_t)lb[2] | ((uint32_t)lb[3] << 16);
        d_bfrag[idx] = o;
    }
}

// layer1 for a 16-unit chunk: fp32 from constant, split to bf16 hi/lo pairs
template<int WOFF, int BOFF>
__device__ __forceinline__ void l1_chunk(int q, const ull* kk,
                                         uint32_t* hv, uint32_t* lv) {
    #pragma unroll
    for (int p = 0; p < 8; p++) {
        const int j0 = q * 16 + 2 * p;
        const int j1 = j0 + 1;
        float h0 = 0.0f, h1 = 0.0f;
        if (j0 < HID) {
            ull acc = cb[BOFF + j0];
            #pragma unroll
            for (int pp = 0; pp < 5; pp++)
                acc = ffma2(kk[pp], cb[WOFF + j0 * 5 + pp], acc);
            float2 u = unpk(acc);
            h0 = fmaxf(u.x + u.y, 0.0f);
        } else if (j0 == HID) h0 = 1.0f;       // bias-fold "ones" column
        if (j1 < HID) {
            ull acc = cb[BOFF + j1];
            #pragma unroll
            for (int pp = 0; pp < 5; pp++)
                acc = ffma2(kk[pp], cb[WOFF + j1 * 5 + pp], acc);
            float2 u = unpk(acc);
            h1 = fmaxf(u.x + u.y, 0.0f);
        } else if (j1 == HID) h1 = 1.0f;
        uint32_t hi;
        asm("cvt.rn.bf16x2.f32 %0, %1, %2;" : "=r"(hi) : "f"(h1), "f"(h0));
        float l0 = h0 - __uint_as_float(hi << 16);
        float l1 = h1 - __uint_as_float(hi & 0xFFFF0000u);
        uint32_t lo;
        asm("cvt.rn.bf16x2.f32 %0, %1, %2;" : "=r"(lo) : "f"(l1), "f"(l0));
        hv[p] = hi; lv[p] = lo;
    }
}

__device__ __forceinline__ void st_tile(char* buf, int lane,
                                        const uint32_t* hv, const uint32_t* lv) {
    *(uint4*)(buf + lane * 48)             = make_uint4(hv[0], hv[1], hv[2], hv[3]);
    *(uint4*)(buf + lane * 48 + 16)        = make_uint4(hv[4], hv[5], hv[6], hv[7]);
    *(uint4*)(buf + 1536 + lane * 48)      = make_uint4(lv[0], lv[1], lv[2], lv[3]);
    *(uint4*)(buf + 1536 + lane * 48 + 16) = make_uint4(lv[4], lv[5], lv[6], lv[7]);
}

// fused layer1 + split-bf16 mma GEMM, software-pipelined over k-chunks with
// double-buffered A tiles (one syncwarp per chunk).
template<int WOFF, int BOFF, int NT>
__device__ __forceinline__ void gemm_branch(
    const uint4* __restrict__ bfrag, const ull* kk,
    char* ht, uint32_t ht_u, uint32_t lmoff, int lane, float (&c)[2][NT][4])
{
    #pragma unroll
    for (int m = 0; m < 2; m++)
        #pragma unroll
        for (int tn = 0; tn < NT; tn++)
            #pragma unroll
            for (int e = 0; e < 4; e++) c[m][tn][e] = 0.0f;

    uint32_t hv[8], lv[8];
    l1_chunk<WOFF, BOFF>(0, kk, hv, lv);
    st_tile(ht, lane, hv, lv);
    __syncwarp();

    #pragma unroll
    for (int q = 0; q < 7; q++) {
        const uint32_t cur = (uint32_t)((q & 1) * 3072);
        uint32_t Ah0[4], Ah1[4], Al0[4], Al1[4];
        ldmA(Ah0, ht_u + cur + lmoff);
        ldmA(Ah1, ht_u + cur + 768 + lmoff);
        ldmA(Al0, ht_u + cur + 1536 + lmoff);
        ldmA(Al1, ht_u + cur + 1536 + 768 + lmoff);
        if (q < 6) {
            l1_chunk<WOFF, BOFF>(q + 1, kk, hv, lv);     // overlaps LDSM latency
            st_tile(ht + ((q + 1) & 1) * 3072, lane, hv, lv);
        }
        const uint4* bq = bfrag + q * NT * 32 + lane;
        #pragma unroll
        for (int tn = 0; tn < NT; tn++) {
            uint4 b = bq[tn * 32];
            mma_bf16(c[0][tn], Ah0, b.x, b.y);   // hi*hi
            mma_bf16(c[0][tn], Ah0, b.z, b.w);   // hi*lo
            mma_bf16(c[0][tn], Al0, b.x, b.y);   // lo*hi
            mma_bf16(c[1][tn], Ah1, b.x, b.y);
            mma_bf16(c[1][tn], Ah1, b.z, b.w);
            mma_bf16(c[1][tn], Al1, b.x, b.y);
        }
        __syncwarp();    // tensor pipe drains while next chunk's LDSM proceeds
    }
}

extern "C" __global__ void __launch_bounds__(THREADS, 2)
net_kernel(const float* __restrict__ s, const float* __restrict__ a,
           float* __restrict__ out, int B)
{
    extern __shared__ __align__(16) char smem[];
    const int t = threadIdx.x;
    const int lane = t & 31;
    const int warp = t >> 5;
    const int lq = lane & 3, lr = lane >> 2;

    // stage B fragments into SMEM
    uint4* bf = (uint4*)(smem + SM_BF);
    for (int i = t; i < NFRAG_LOC + NFRAG_VAL; i += THREADS) bf[i] = d_bfrag[i];
    __syncthreads();

    char* ht = smem + SM_HT + warp * 6144;
    __half* ewp = (__half*)(smem + SM_EW + warp * 2560);
    const uint32_t ht_u = smem_u32(ht);
    const uint32_t lmoff = (uint32_t)((lane & 15) * 48 + ((lane >> 4) << 4));

    const int base = blockIdx.x * 256 + warp * 32;
    const int myrow = base + lane;
    const int rc = myrow < B ? myrow : B - 1;

    ull kk[5];
    {
        const ull* sp = (const ull*)(s + (size_t)rc * SD);
        #pragma unroll
        for (int p = 0; p < 5; p++) kk[p] = sp[p];
    }

    // ---- loc branch GEMM (N=64: 30 centroid (x,y) pairs + padding) ----
    float cl[2][8][4];
    gemm_branch<CL1T, CBL1, 8>(bf, kk, ht, ht_u, lmoff, lane, cl);

    // action vectors for my 4 epilogue rows
    float2 av[2][2];
    #pragma unroll
    for (int m = 0; m < 2; m++)
        #pragma unroll
        for (int h = 0; h < 2; h++) {
            int r = base + m * 16 + lr + h * 8;
            r = r < B ? r : B - 1;
            av[m][h] = *(const float2*)(a + (size_t)r * 2);
        }

    // ---- loc epilogue: centroids -> ew (fp16 SMEM relay) + den partials ----
    float den[4] = {0.0f, 0.0f, 0.0f, 0.0f};
    #pragma unroll
    for (int m = 0; m < 2; m++) {
        #pragma unroll
        for (int tn = 0; tn < 8; tn++) {
            int n = tn * 4 + lq;
            float e0 = 0.0f, e1 = 0.0f;
            if (n < NC) {
                float px = MAXA_F * tanh_fast(cl[m][tn][0]);
                float py = MAXA_F * tanh_fast(cl[m][tn][1]);
                float dx = px - av[m][0].x, dy = py - av[m][0].y;
                e0 = __expf(-BETA_F * sqrtf(fmaf(dx, dx, dy * dy)));
                px = MAXA_F * tanh_fast(cl[m][tn][2]);
                py = MAXA_F * tanh_fast(cl[m][tn][3]);
                dx = px - av[m][1].x; dy = py - av[m][1].y;
                e1 = __expf(-BETA_F * sqrtf(fmaf(dx, dx, dy * dy)));
            }
            ewp[(m * 16 + lr) * 40 + n]     = __float2half(e0);
            ewp[(m * 16 + lr + 8) * 40 + n] = __float2half(e1);
            den[m * 2 + 0] += e0;
            den[m * 2 + 1] += e1;
        }
    }
    #pragma unroll
    for (int i = 0; i < 4; i++) {
        den[i] += __shfl_xor_sync(0xFFFFFFFFu, den[i], 1);
        den[i] += __shfl_xor_sync(0xFFFFFFFFu, den[i], 2);
    }
    __syncwarp();

    // ---- val branch GEMM (N=32: 30 values + padding) ----
    float cv[2][4][4];
    gemm_branch<CW1T, CB1, 4>(bf + NFRAG_LOC, kk, ht, ht_u, lmoff, lane, cv);

    // ---- val epilogue: num = sum ew*v (ew via fp16 SMEM, padded n have ew=0) ----
    float num[4] = {0.0f, 0.0f, 0.0f, 0.0f};
    #pragma unroll
    for (int m = 0; m < 2; m++) {
        #pragma unroll
        for (int tv = 0; tv < 4; tv++) {
            int n0 = tv * 8 + 2 * lq;
            float2 e0 = __half22float2(*(__half2*)(ewp + (m * 16 + lr) * 40 + n0));
            float2 e1 = __half22float2(*(__half2*)(ewp + (m * 16 + lr + 8) * 40 + n0));
            num[m * 2 + 0] += cv[m][tv][0] * e0.x + cv[m][tv][1] * e0.y;
            num[m * 2 + 1] += cv[m][tv][2] * e1.x + cv[m][tv][3] * e1.y;
        }
    }
    #pragma unroll
    for (int i = 0; i < 4; i++) {
        num[i] += __shfl_xor_sync(0xFFFFFFFFu, num[i], 1);
        num[i] += __shfl_xor_sync(0xFFFFFFFFu, num[i], 2);
    }
    if (lq == 0) {
        #pragma unroll
        for (int m = 0; m < 2; m++)
            #pragma unroll
            for (int h = 0; h < 2; h++) {
                int r = base + m * 16 + lr + h * 8;
                if (r < B) out[r] = num[m * 2 + h] / den[m * 2 + h];
            }
    }
}

extern "C" void kernel_launch(void* const* d_in, const int* in_sizes, int n_in,
                              void* d_out, int out_size) {
    const float* s   = (const float*)d_in[0];
    const float* a   = (const float*)d_in[1];
    const float* W1  = (const float*)d_in[2];
    const float* b1  = (const float*)d_in[3];
    const float* W2  = (const float*)d_in[4];
    const float* b2  = (const float*)d_in[5];
    const float* L1  = (const float*)d_in[6];
    const float* bl1 = (const float*)d_in[7];
    const float* WL2 = (const float*)d_in[8];
    const float* bL2 = (const float*)d_in[9];
    float* out = (float*)d_out;

    const int B = in_sizes[0] / SD;
    const int blocks = (B + 255) / 256;

    prep_kernel<<<8, 256>>>(W1, b1, W2, b2, L1, bl1, WL2, bL2);
    void* scratch_ptr = nullptr;
    cudaGetSymbolAddress(&scratch_ptr, d_scratch);
    cudaMemcpyToSymbolAsync(cb, scratch_ptr, CONST_ULL * sizeof(ull), 0,
                            cudaMemcpyDeviceToDevice, 0);

    cudaFuncSetAttribute((const void*)net_kernel,
                         cudaFuncAttributeMaxDynamicSharedMemorySize, SMEM_BYTES);
    net_kernel<<<blocks, THREADS, SMEM_BYTES>>>(s, a, out, B);
}

// round 9
// speedup vs baseline: 1.5453x; 1.5453x over previous
#include <cuda_runtime.h>
#include <cuda_bf16.h>
#include <cstdint>

#define THREADS 256
#define HID 100
#define NC 30
#define SD 10
#define BETA_F 3.0f
#define MAXA_F 5.0f

typedef unsigned long long ull;

// ---- precomputed mma B fragments (uint4 = hi b0,b1, lo b0,b1) ----
#define NFRAG2_LOC (7 * 8 * 32)    // layer2 loc: 7 k-chunks x 8 n-tiles x 32 lanes
#define NFRAG2_VAL (7 * 4 * 32)    // layer2 val
#define NFRAG1     (13 * 32)       // layer1 (per branch): 13 n-tiles x 32 lanes
#define NFRAG_TOT  (NFRAG2_LOC + NFRAG2_VAL + 2 * NFRAG1)
__device__ uint4 d_bfrag[NFRAG_TOT];

// ---- SMEM layout (uint4 units for frags, then ew relay) ----
#define U4_BF2_LOC 0
#define U4_BF2_VAL 1792
#define U4_BF1_LOC 2688
#define U4_BF1_VAL 3104
#define SM_EW_BYTE (3520 * 16)            // 56320
#define SMEM_BYTES (SM_EW_BYTE + 8 * 32 * 40 * 4)   // + 40960 = 97280

__device__ __forceinline__ float tanh_fast(float x) {
    float e = __expf(2.0f * x);
    return 1.0f - __fdividef(2.0f, e + 1.0f);
}
__device__ __forceinline__ void mma_bf16(float* c, const uint32_t* A,
                                         uint32_t b0, uint32_t b1) {
    asm volatile(
        "mma.sync.aligned.m16n8k16.row.col.f32.bf16.bf16.f32 "
        "{%0,%1,%2,%3}, {%4,%5,%6,%7}, {%8,%9}, {%0,%1,%2,%3};"
        : "+f"(c[0]), "+f"(c[1]), "+f"(c[2]), "+f"(c[3])
        : "r"(A[0]), "r"(A[1]), "r"(A[2]), "r"(A[3]), "r"(b0), "r"(b1));
}
__device__ __forceinline__ uint32_t cvt2(float hi, float lo) {
    uint32_t r;
    asm("cvt.rn.bf16x2.f32 %0, %1, %2;" : "=r"(r) : "f"(hi), "f"(lo));
    return r;
}
// split float2 v -> (hi bf16x2, lo bf16x2)
__device__ __forceinline__ void split2(float vx, float vy, uint32_t& h, uint32_t& l) {
    h = cvt2(vy, vx);
    float lx = vx - __uint_as_float(h << 16);
    float ly = vy - __uint_as_float(h & 0xFFFF0000u);
    l = cvt2(ly, lx);
}

// ---- prep: build all B fragments in mma lane order ----
extern "C" __global__ void prep_kernel(const float* __restrict__ W1,
                                       const float* __restrict__ b1,
                                       const float* __restrict__ W2,
                                       const float* __restrict__ b2,
                                       const float* __restrict__ L1,
                                       const float* __restrict__ bl1,
                                       const float* __restrict__ WL2,
                                       const float* __restrict__ bL2) {
    int t = blockIdx.x * blockDim.x + threadIdx.x;
    int stride = gridDim.x * blockDim.x;
    for (int idx = t; idx < NFRAG_TOT; idx += stride) {
        float v[4];
        if (idx < NFRAG2_LOC + NFRAG2_VAL) {            // ---- layer2 frags ----
            bool isloc = idx < NFRAG2_LOC;
            int rel = isloc ? idx : idx - NFRAG2_LOC;
            int lane = rel & 31;
            int f = rel >> 5;
            int nt = isloc ? 8 : 4;
            int q = f / nt, tn = f % nt;
            int k0 = q * 16 + 2 * (lane & 3);
            int n  = tn * 8 + (lane >> 2);
            #pragma unroll
            for (int e = 0; e < 4; e++) {
                int k = k0 + (e >> 1) * 8 + (e & 1);
                float x = 0.0f;
                if (isloc) {
                    if (n < 60) {
                        if (k < HID)       x = WL2[(n >> 1) * 200 + k * 2 + (n & 1)];
                        else if (k == HID) x = bL2[n];
                    }
                } else {
                    if (n < NC) {
                        if (k < HID)       x = W2[k * NC + n];
                        else if (k == HID) x = b2[n];
                    }
                }
                v[e] = x;
            }
        } else {                                        // ---- layer1 frags ----
            int rel = idx - (NFRAG2_LOC + NFRAG2_VAL);
            bool isloc = rel < NFRAG1;
            if (!isloc) rel -= NFRAG1;
            int lane = rel & 31;
            int tn = rel >> 5;                          // 0..12
            int k0 = 2 * (lane & 3);
            int n  = tn * 8 + (lane >> 2);              // hidden unit j
            const float* Wm = isloc ? L1 : W1;
            const float* bm = isloc ? bl1 : b1;
            #pragma unroll
            for (int e = 0; e < 4; e++) {
                int k = k0 + (e >> 1) * 8 + (e & 1);
                float x = 0.0f;
                if (n < HID) {
                    if (k < SD)       x = Wm[k * HID + n];
                    else if (k == SD) x = bm[n];
                }
                v[e] = x;
            }
        }
        unsigned short hb[4], lb[4];
        #pragma unroll
        for (int e = 0; e < 4; e++) {
            __nv_bfloat16 h = __float2bfloat16(v[e]);
            hb[e] = __bfloat16_as_ushort(h);
            lb[e] = __bfloat16_as_ushort(__float2bfloat16(v[e] - __bfloat162float(h)));
        }
        uint4 o;
        o.x = (uint32_t)hb[0] | ((uint32_t)hb[1] << 16);
        o.y = (uint32_t)hb[2] | ((uint32_t)hb[3] << 16);
        o.z = (uint32_t)lb[0] | ((uint32_t)lb[1] << 16);
        o.w = (uint32_t)lb[2] | ((uint32_t)lb[3] << 16);
        d_bfrag[idx] = o;
    }
}

// one branch: layer1 (tensor, K=16) -> register relu/split -> layer2 (tensor)
template<int NT>
__device__ __forceinline__ void branch_gemm(
    const uint4* __restrict__ bf1, const uint4* __restrict__ bf2,
    const uint32_t (&Ash)[2][4], const uint32_t (&Asl)[2][4],
    int lane, int lq, float (&c)[2][NT][4])
{
    #pragma unroll
    for (int mt = 0; mt < 2; mt++)
        #pragma unroll
        for (int tn = 0; tn < NT; tn++)
            #pragma unroll
            for (int e = 0; e < 4; e++) c[mt][tn][e] = 0.0f;

    #pragma unroll
    for (int q = 0; q < 7; q++) {
        // ---- layer1: C tiles for hidden cols [16q, 16q+16) ----
        float C[2][2][4];
        #pragma unroll
        for (int mt = 0; mt < 2; mt++)
            #pragma unroll
            for (int h = 0; h < 2; h++)
                #pragma unroll
                for (int e = 0; e < 4; e++) C[mt][h][e] = 0.0f;

        #pragma unroll
        for (int nt2 = 0; nt2 < 2; nt2++) {
            const int tn = 2 * q + nt2;
            if (tn < 13) {
                uint4 b = bf1[tn * 32 + lane];
                #pragma unroll
                for (int mt = 0; mt < 2; mt++) {
                    mma_bf16(C[mt][nt2], Ash[mt], b.x, b.y);   // hi*hi
                    mma_bf16(C[mt][nt2], Ash[mt], b.z, b.w);   // hi*lo
                    mma_bf16(C[mt][nt2], Asl[mt], b.x, b.y);   // lo*hi
                }
            }
        }
        // ---- relu + split -> layer2 A fragments (pure register) ----
        uint32_t Ah[2][4], Al[2][4];
        #pragma unroll
        for (int mt = 0; mt < 2; mt++) {
            #pragma unroll
            for (int h = 0; h < 2; h++) {
                float v0 = fmaxf(C[mt][h][0], 0.0f);
                float v1 = fmaxf(C[mt][h][1], 0.0f);
                float v2 = fmaxf(C[mt][h][2], 0.0f);
                float v3 = fmaxf(C[mt][h][3], 0.0f);
                if (q == 6) {                 // cols 96..111: ones col @100, 104+ zero
                    if (h == 0) {
                        if (lq == 2) { v0 = 1.0f; v2 = 1.0f; }
                    } else {
                        v0 = v1 = v2 = v3 = 0.0f;
                    }
                }
                split2(v0, v1, Ah[mt][2 * h + 0], Al[mt][2 * h + 0]);   // row lr
                split2(v2, v3, Ah[mt][2 * h + 1], Al[mt][2 * h + 1]);   // row lr+8
            }
        }
        // ---- layer2 ----
        const uint4* bq = bf2 + q * NT * 32 + lane;
        #pragma unroll
        for (int tn = 0; tn < NT; tn++) {
            uint4 b = bq[tn * 32];
            #pragma unroll
            for (int mt = 0; mt < 2; mt++) {
                mma_bf16(c[mt][tn], Ah[mt], b.x, b.y);
                mma_bf16(c[mt][tn], Ah[mt], b.z, b.w);
                mma_bf16(c[mt][tn], Al[mt], b.x, b.y);
            }
        }
    }
}

extern "C" __global__ void __launch_bounds__(THREADS, 2)
net_kernel(const float* __restrict__ s, const float* __restrict__ a,
           float* __restrict__ out, int B)
{
    extern __shared__ __align__(16) char smem[];
    const int t = threadIdx.x;
    const int lane = t & 31;
    const int warp = t >> 5;
    const int lq = lane & 3, lr = lane >> 2;

    // stage all B fragments into SMEM
    uint4* bf = (uint4*)smem;
    for (int i = t; i < NFRAG_TOT; i += THREADS) bf[i] = d_bfrag[i];
    __syncthreads();

    const uint4* bf2_loc = bf + U4_BF2_LOC;
    const uint4* bf2_val = bf + U4_BF2_VAL;
    const uint4* bf1_loc = bf + U4_BF1_LOC;
    const uint4* bf1_val = bf + U4_BF1_VAL;
    float* ewp = (float*)(smem + SM_EW_BYTE) + warp * (32 * 40);

    const int base = blockIdx.x * 256 + warp * 32;

    // ---- build A fragments of s (K=16: 10 inputs + ones col @10 + pad) ----
    uint32_t Ash[2][4], Asl[2][4];
    #pragma unroll
    for (int mt = 0; mt < 2; mt++) {
        #pragma unroll
        for (int rr = 0; rr < 2; rr++) {      // rr 0: row lr, 1: row lr+8
            int r = base + mt * 16 + lr + rr * 8;
            r = r < B ? r : B - 1;
            const float* sr = s + (size_t)r * SD;
            float2 v01 = *(const float2*)(sr + 2 * lq);       // cols 2lq,2lq+1 (<8)
            float2 v23;                                       // cols 8+2lq, 9+2lq
            if (lq == 0)      v23 = *(const float2*)(sr + 8);
            else if (lq == 1) v23 = make_float2(1.0f, 0.0f);  // ones col @10
            else              v23 = make_float2(0.0f, 0.0f);
            split2(v01.x, v01.y, Ash[mt][rr],     Asl[mt][rr]);
            split2(v23.x, v23.y, Ash[mt][2 + rr], Asl[mt][2 + rr]);
        }
    }

    // ---- loc branch: 30 centroid (x,y) pairs in N=64 ----
    float cl[2][8][4];
    branch_gemm<8>(bf1_loc, bf2_loc, Ash, Asl, lane, lq, cl);

    float2 av[2][2];
    #pragma unroll
    for (int m = 0; m < 2; m++)
        #pragma unroll
        for (int h = 0; h < 2; h++) {
            int r = base + m * 16 + lr + h * 8;
            r = r < B ? r : B - 1;
            av[m][h] = *(const float2*)(a + (size_t)r * 2);
        }

    // ---- loc epilogue: centroids -> ew (fp32 SMEM relay) + den ----
    float den[4] = {0.0f, 0.0f, 0.0f, 0.0f};
    #pragma unroll
    for (int m = 0; m < 2; m++) {
        #pragma unroll
        for (int tn = 0; tn < 8; tn++) {
            int n = tn * 4 + lq;
            float e0 = 0.0f, e1 = 0.0f;
            if (n < NC) {
                float px = MAXA_F * tanh_fast(cl[m][tn][0]);
                float py = MAXA_F * tanh_fast(cl[m][tn][1]);
                float dx = px - av[m][0].x, dy = py - av[m][0].y;
                e0 = __expf(-BETA_F * sqrtf(fmaf(dx, dx, dy * dy)));
                px = MAXA_F * tanh_fast(cl[m][tn][2]);
                py = MAXA_F * tanh_fast(cl[m][tn][3]);
                dx = px - av[m][1].x; dy = py - av[m][1].y;
                e1 = __expf(-BETA_F * sqrtf(fmaf(dx, dx, dy * dy)));
            }
            ewp[(m * 16 + lr) * 40 + n]     = e0;
            ewp[(m * 16 + lr + 8) * 40 + n] = e1;
            den[m * 2 + 0] += e0;
            den[m * 2 + 1] += e1;
        }
    }
    #pragma unroll
    for (int i = 0; i < 4; i++) {
        den[i] += __shfl_xor_sync(0xFFFFFFFFu, den[i], 1);
        den[i] += __shfl_xor_sync(0xFFFFFFFFu, den[i], 2);
    }
    __syncwarp();

    // ---- val branch: 30 values in N=32 ----
    float cv[2][4][4];
    branch_gemm<4>(bf1_val, bf2_val, Ash, Asl, lane, lq, cv);

    // ---- val epilogue: num = sum ew*v ----
    float num[4] = {0.0f, 0.0f, 0.0f, 0.0f};
    #pragma unroll
    for (int m = 0; m < 2; m++) {
        #pragma unroll
        for (int tv = 0; tv < 4; tv++) {
            int n0 = tv * 8 + 2 * lq;
            float2 e0 = *(float2*)(ewp + (m * 16 + lr) * 40 + n0);
            float2 e1 = *(float2*)(ewp + (m * 16 + lr + 8) * 40 + n0);
            num[m * 2 + 0] += cv[m][tv][0] * e0.x + cv[m][tv][1] * e0.y;
            num[m * 2 + 1] += cv[m][tv][2] * e1.x + cv[m][tv][3] * e1.y;
        }
    }
    #pragma unroll
    for (int i = 0; i < 4; i++) {
        num[i] += __shfl_xor_sync(0xFFFFFFFFu, num[i], 1);
        num[i] += __shfl_xor_sync(0xFFFFFFFFu, num[i], 2);
    }
    if (lq == 0) {
        #pragma unroll
        for (int m = 0; m < 2; m++)
            #pragma unroll
            for (int h = 0; h < 2; h++) {
                int r = base + m * 16 + lr + h * 8;
                if (r < B) out[r] = num[m * 2 + h] / den[m * 2 + h];
            }
    }
}

extern "C" void kernel_launch(void* const* d_in, const int* in_sizes, int n_in,
                              void* d_out, int out_size) {
    const float* s   = (const float*)d_in[0];
    const float* a   = (const float*)d_in[1];
    const float* W1  = (const float*)d_in[2];
    const float* b1  = (const float*)d_in[3];
    const float* W2  = (const float*)d_in[4];
    const float* b2  = (const float*)d_in[5];
    const float* L1  = (const float*)d_in[6];
    const float* bl1 = (const float*)d_in[7];
    const float* WL2 = (const float*)d_in[8];
    const float* bL2 = (const float*)d_in[9];
    float* out = (float*)d_out;

    const int B = in_sizes[0] / SD;
    const int blocks = (B + 255) / 256;

    prep_kernel<<<8, 256>>>(W1, b1, W2, b2, L1, bl1, WL2, bL2);

    cudaFuncSetAttribute((const void*)net_kernel,
                         cudaFuncAttributeMaxDynamicSharedMemorySize, SMEM_BYTES);
    net_kernel<<<blocks, THREADS, SMEM_BYTES>>>(s, a, out, B);
}

// round 10
// speedup vs baseline: 1.6697x; 1.0805x over previous
#include <cuda_runtime.h>
#include <cuda_bf16.h>
#include <cstdint>

#define THREADS 128
#define HID 100
#define NC 30
#define SD 10
#define BETA_F 3.0f
#define MAXA_F 5.0f

// ---- precomputed mma B fragments (uint4 = hi b0,b1, lo b0,b1) ----
#define NFRAG2_LOC (7 * 8 * 32)    // layer2 loc: 7 k-chunks x 8 n-tiles x 32 lanes
#define NFRAG2_VAL (7 * 4 * 32)    // layer2 val
#define NFRAG1     (13 * 32)       // layer1 (per branch): 13 n-tiles x 32 lanes
#define NFRAG_TOT  (NFRAG2_LOC + NFRAG2_VAL + 2 * NFRAG1)
__device__ uint4 d_bfrag[NFRAG_TOT];

// ---- SMEM: ew relay only (per warp: 16 rows x 44 floats, conflict-free) ----
#define EW_STRIDE 44
#define SMEM_BYTES (4 * 16 * EW_STRIDE * 4)   // 11264 B -> 6 CTAs/SM fit easily

__device__ __forceinline__ float tanh_fast(float x) {
    float e = __expf(2.0f * x);
    return 1.0f - __fdividef(2.0f, e + 1.0f);
}
__device__ __forceinline__ void mma_bf16(float* c, const uint32_t* A,
                                         uint32_t b0, uint32_t b1) {
    asm volatile(
        "mma.sync.aligned.m16n8k16.row.col.f32.bf16.bf16.f32 "
        "{%0,%1,%2,%3}, {%4,%5,%6,%7}, {%8,%9}, {%0,%1,%2,%3};"
        : "+f"(c[0]), "+f"(c[1]), "+f"(c[2]), "+f"(c[3])
        : "r"(A[0]), "r"(A[1]), "r"(A[2]), "r"(A[3]), "r"(b0), "r"(b1));
}
__device__ __forceinline__ uint32_t cvt2(float hi, float lo) {
    uint32_t r;
    asm("cvt.rn.bf16x2.f32 %0, %1, %2;" : "=r"(r) : "f"(hi), "f"(lo));
    return r;
}
// split (vx, vy) -> (hi bf16x2, lo bf16x2)
__device__ __forceinline__ void split2(float vx, float vy, uint32_t& h, uint32_t& l) {
    h = cvt2(vy, vx);
    float lx = vx - __uint_as_float(h << 16);
    float ly = vy - __uint_as_float(h & 0xFFFF0000u);
    l = cvt2(ly, lx);
}

// ---- prep: build all B fragments in mma lane order (identical to R9) ----
extern "C" __global__ void prep_kernel(const float* __restrict__ W1,
                                       const float* __restrict__ b1,
                                       const float* __restrict__ W2,
                                       const float* __restrict__ b2,
                                       const float* __restrict__ L1,
                                       const float* __restrict__ bl1,
                                       const float* __restrict__ WL2,
                                       const float* __restrict__ bL2) {
    int t = blockIdx.x * blockDim.x + threadIdx.x;
    int stride = gridDim.x * blockDim.x;
    for (int idx = t; idx < NFRAG_TOT; idx += stride) {
        float v[4];
        if (idx < NFRAG2_LOC + NFRAG2_VAL) {            // ---- layer2 frags ----
            bool isloc = idx < NFRAG2_LOC;
            int rel = isloc ? idx : idx - NFRAG2_LOC;
            int lane = rel & 31;
            int f = rel >> 5;
            int nt = isloc ? 8 : 4;
            int q = f / nt, tn = f % nt;
            int k0 = q * 16 + 2 * (lane & 3);
            int n  = tn * 8 + (lane >> 2);
            #pragma unroll
            for (int e = 0; e < 4; e++) {
                int k = k0 + (e >> 1) * 8 + (e & 1);
                float x = 0.0f;
                if (isloc) {
                    if (n < 60) {
                        if (k < HID)       x = WL2[(n >> 1) * 200 + k * 2 + (n & 1)];
                        else if (k == HID) x = bL2[n];
                    }
                } else {
                    if (n < NC) {
                        if (k < HID)       x = W2[k * NC + n];
                        else if (k == HID) x = b2[n];
                    }
                }
                v[e] = x;
            }
        } else {                                        // ---- layer1 frags ----
            int rel = idx - (NFRAG2_LOC + NFRAG2_VAL);
            bool isloc = rel < NFRAG1;
            if (!isloc) rel -= NFRAG1;
            int lane = rel & 31;
            int tn = rel >> 5;                          // 0..12
            int k0 = 2 * (lane & 3);
            int n  = tn * 8 + (lane >> 2);              // hidden unit j
            const float* Wm = isloc ? L1 : W1;
            const float* bm = isloc ? bl1 : b1;
            #pragma unroll
            for (int e = 0; e < 4; e++) {
                int k = k0 + (e >> 1) * 8 + (e & 1);
                float x = 0.0f;
                if (n < HID) {
                    if (k < SD)       x = Wm[k * HID + n];
                    else if (k == SD) x = bm[n];
                }
                v[e] = x;
            }
        }
        unsigned short hb[4], lb[4];
        #pragma unroll
        for (int e = 0; e < 4; e++) {
            __nv_bfloat16 h = __float2bfloat16(v[e]);
            hb[e] = __bfloat16_as_ushort(h);
            lb[e] = __bfloat16_as_ushort(__float2bfloat16(v[e] - __bfloat162float(h)));
        }
        uint4 o;
        o.x = (uint32_t)hb[0] | ((uint32_t)hb[1] << 16);
        o.y = (uint32_t)hb[2] | ((uint32_t)hb[3] << 16);
        o.z = (uint32_t)lb[0] | ((uint32_t)lb[1] << 16);
        o.w = (uint32_t)lb[2] | ((uint32_t)lb[3] << 16);
        d_bfrag[idx] = o;
    }
}

// one branch, 16 rows/warp: layer1 (tensor) -> register relu/split -> layer2
template<int NT>
__device__ __forceinline__ void branch_gemm(
    const uint4* __restrict__ bf1, const uint4* __restrict__ bf2,
    const uint32_t (&Ash)[4], const uint32_t (&Asl)[4],
    int lane, int lq, float (&c)[NT][4])
{
    #pragma unroll
    for (int tn = 0; tn < NT; tn++)
        #pragma unroll
        for (int e = 0; e < 4; e++) c[tn][e] = 0.0f;

    #pragma unroll
    for (int q = 0; q < 7; q++) {
        // ---- layer1: hidden cols [16q, 16q+16) ----
        float C[2][4];
        #pragma unroll
        for (int h = 0; h < 2; h++)
            #pragma unroll
            for (int e = 0; e < 4; e++) C[h][e] = 0.0f;

        #pragma unroll
        for (int nt2 = 0; nt2 < 2; nt2++) {
            const int tn = 2 * q + nt2;
            if (tn < 13) {
                uint4 b = __ldg(&bf1[tn * 32 + lane]);
                mma_bf16(C[nt2], Ash, b.x, b.y);   // hi*hi
                mma_bf16(C[nt2], Ash, b.z, b.w);   // hi*lo
                mma_bf16(C[nt2], Asl, b.x, b.y);   // lo*hi
            }
        }
        // ---- relu + split -> layer2 A fragments (registers only) ----
        uint32_t Ah[4], Al[4];
        #pragma unroll
        for (int h = 0; h < 2; h++) {
            float v0 = fmaxf(C[h][0], 0.0f);
            float v1 = fmaxf(C[h][1], 0.0f);
            float v2 = fmaxf(C[h][2], 0.0f);
            float v3 = fmaxf(C[h][3], 0.0f);
            if (q == 6) {                  // cols 96..111: ones col @100, rest 0
                if (h == 0) {
                    if (lq == 2) { v0 = 1.0f; v2 = 1.0f; }
                } else {
                    v0 = v1 = v2 = v3 = 0.0f;
                }
            }
            split2(v0, v1, Ah[2 * h + 0], Al[2 * h + 0]);   // row lr
            split2(v2, v3, Ah[2 * h + 1], Al[2 * h + 1]);   // row lr+8
        }
        // ---- layer2 ----
        const uint4* bq = bf2 + q * NT * 32 + lane;
        #pragma unroll
        for (int tn = 0; tn < NT; tn++) {
            uint4 b = __ldg(&bq[tn * 32]);
            mma_bf16(c[tn], Ah, b.x, b.y);
            mma_bf16(c[tn], Ah, b.z, b.w);
            mma_bf16(c[tn], Al, b.x, b.y);
        }
    }
}

extern "C" __global__ void __launch_bounds__(THREADS, 6)
net_kernel(const float* __restrict__ s, const float* __restrict__ a,
           float* __restrict__ out, int B)
{
    extern __shared__ __align__(16) float ews[];
    const int t = threadIdx.x;
    const int lane = t & 31;
    const int warp = t >> 5;
    const int lq = lane & 3, lr = lane >> 2;
    float* ewp = ews + warp * (16 * EW_STRIDE);

    const int base = blockIdx.x * 64 + warp * 16;

    // ---- A fragments of s (K=16: 10 inputs + ones col @10 + pad) ----
    uint32_t Ash[4], Asl[4];
    #pragma unroll
    for (int rr = 0; rr < 2; rr++) {              // rr 0: row lr, 1: row lr+8
        int r = base + lr + rr * 8;
        r = r < B ? r : B - 1;
        const float* sr = s + (size_t)r * SD;
        float2 v01 = *(const float2*)(sr + 2 * lq);       // cols 2lq, 2lq+1
        float2 v23;                                       // cols 8+2lq, 9+2lq
        if (lq == 0)      v23 = *(const float2*)(sr + 8);
        else if (lq == 1) v23 = make_float2(1.0f, 0.0f);  // ones col @10
        else              v23 = make_float2(0.0f, 0.0f);
        split2(v01.x, v01.y, Ash[rr],     Asl[rr]);
        split2(v23.x, v23.y, Ash[2 + rr], Asl[2 + rr]);
    }

    const uint4* bf2_loc = d_bfrag;
    const uint4* bf2_val = d_bfrag + NFRAG2_LOC;
    const uint4* bf1_loc = d_bfrag + NFRAG2_LOC + NFRAG2_VAL;
    const uint4* bf1_val = bf1_loc + NFRAG1;

    // ---- loc branch: 30 centroid (x,y) pairs in N=64 ----
    float cl[8][4];
    branch_gemm<8>(bf1_loc, bf2_loc, Ash, Asl, lane, lq, cl);

    float2 av0, av1;
    { int r = base + lr;     r = r < B ? r : B - 1; av0 = *(const float2*)(a + (size_t)r * 2); }
    { int r = base + lr + 8; r = r < B ? r : B - 1; av1 = *(const float2*)(a + (size_t)r * 2); }

    // ---- loc epilogue: centroids -> ew (SMEM relay) + den ----
    float den0 = 0.0f, den1 = 0.0f;
    #pragma unroll
    for (int tn = 0; tn < 8; tn++) {
        int n = tn * 4 + lq;
        float e0 = 0.0f, e1 = 0.0f;
        if (n < NC) {
            float px = MAXA_F * tanh_fast(cl[tn][0]);
            float py = MAXA_F * tanh_fast(cl[tn][1]);
            float dx = px - av0.x, dy = py - av0.y;
            e0 = __expf(-BETA_F * sqrtf(fmaf(dx, dx, dy * dy)));
            px = MAXA_F * tanh_fast(cl[tn][2]);
            py = MAXA_F * tanh_fast(cl[tn][3]);
            dx = px - av1.x; dy = py - av1.y;
            e1 = __expf(-BETA_F * sqrtf(fmaf(dx, dx, dy * dy)));
        }
        ewp[lr * EW_STRIDE + n]       = e0;
        ewp[(lr + 8) * EW_STRIDE + n] = e1;
        den0 += e0;
        den1 += e1;
    }
    den0 += __shfl_xor_sync(0xFFFFFFFFu, den0, 1);
    den0 += __shfl_xor_sync(0xFFFFFFFFu, den0, 2);
    den1 += __shfl_xor_sync(0xFFFFFFFFu, den1, 1);
    den1 += __shfl_xor_sync(0xFFFFFFFFu, den1, 2);
    __syncwarp();

    // ---- val branch: 30 values in N=32 ----
    float cv[4][4];
    branch_gemm<4>(bf1_val, bf2_val, Ash, Asl, lane, lq, cv);

    // ---- val epilogue: num = sum ew*v ----
    float num0 = 0.0f, num1 = 0.0f;
    #pragma unroll
    for (int tv = 0; tv < 4; tv++) {
        int n0 = tv * 8 + 2 * lq;
        float2 e0 = *(float2*)(ewp + lr * EW_STRIDE + n0);
        float2 e1 = *(float2*)(ewp + (lr + 8) * EW_STRIDE + n0);
        num0 += cv[tv][0] * e0.x + cv[tv][1] * e0.y;
        num1 += cv[tv][2] * e1.x + cv[tv][3] * e1.y;
    }
    num0 += __shfl_xor_sync(0xFFFFFFFFu, num0, 1);
    num0 += __shfl_xor_sync(0xFFFFFFFFu, num0, 2);
    num1 += __shfl_xor_sync(0xFFFFFFFFu, num1, 1);
    num1 += __shfl_xor_sync(0xFFFFFFFFu, num1, 2);
    if (lq == 0) {
        int r0 = base + lr, r1 = base + lr + 8;
        if (r0 < B) out[r0] = num0 / den0;
        if (r1 < B) out[r1] = num1 / den1;
    }
}

extern "C" void kernel_launch(void* const* d_in, const int* in_sizes, int n_in,
                              void* d_out, int out_size) {
    const float* s   = (const float*)d_in[0];
    const float* a   = (const float*)d_in[1];
    const float* W1  = (const float*)d_in[2];
    const float* b1  = (const float*)d_in[3];
    const float* W2  = (const float*)d_in[4];
    const float* b2  = (const float*)d_in[5];
    const float* L1  = (const float*)d_in[6];
    const float* bl1 = (const float*)d_in[7];
    const float* WL2 = (const float*)d_in[8];
    const float* bL2 = (const float*)d_in[9];
    float* out = (float*)d_out;

    const int B = in_sizes[0] / SD;
    const int blocks = (B + 63) / 64;

    prep_kernel<<<8, 256>>>(W1, b1, W2, b2, L1, bl1, WL2, bL2);

    net_kernel<<<blocks, THREADS, SMEM_BYTES>>>(s, a, out, B);
}